// round 9
// baseline (speedup 1.0000x reference)
#include <cuda_runtime.h>
#include <cuda_bf16.h>
#include <math.h>
#include <stdint.h>

#define BB   32
#define EE   8
#define HW   196
#define NP   224          // padded N (196 -> 224)
#define EPS  1e-5f

typedef unsigned long long ull;
typedef __nv_bfloat16 bf16;

// ---------------- scratch (device globals; no runtime allocation) -------------
__device__ float g_pooled[BB * 1024];
__device__ float g_rw[BB * EE];
__device__ float g_o1[BB * 256 * HW];
__device__ float g_o2[BB * 256 * HW];
__device__ float g_pp[BB * 256 * 4];          // per-(b,row,nblock) pooling partials
__device__ bf16  g_cwh[BB * 256 * 2304];
__device__ bf16  g_cwl[BB * 256 * 2304];
__device__ bf16  g_xth[BB * NP * 2304];
__device__ bf16  g_xtl[BB * NP * 2304];

// ---------------- helpers -------------------------------------------------------
__device__ __forceinline__ void cp16(void* s, const void* g) {
    unsigned a = (unsigned)__cvta_generic_to_shared(s);
    asm volatile("cp.async.cg.shared.global [%0], [%1], 16;" :: "r"(a), "l"(g));
}
#define CP_COMMIT() asm volatile("cp.async.commit_group;" ::: "memory")

__device__ __forceinline__ uint32_t smem_u32(const void* p) {
    return (uint32_t)__cvta_generic_to_shared(p);
}
__device__ __forceinline__ void ldsm_x4(uint32_t* r, uint32_t a) {
    asm volatile("ldmatrix.sync.aligned.m8n8.x4.shared.b16 {%0,%1,%2,%3}, [%4];"
                 : "=r"(r[0]), "=r"(r[1]), "=r"(r[2]), "=r"(r[3]) : "r"(a));
}
__device__ __forceinline__ void ldsm_x2(uint32_t* r, uint32_t a) {
    asm volatile("ldmatrix.sync.aligned.m8n8.x2.shared.b16 {%0,%1}, [%2];"
                 : "=r"(r[0]), "=r"(r[1]) : "r"(a));
}
__device__ __forceinline__ void mma_bf16(float* d, const uint32_t* a, const uint32_t* b) {
    asm volatile("mma.sync.aligned.m16n8k16.row.col.f32.bf16.bf16.f32 "
                 "{%0,%1,%2,%3}, {%4,%5,%6,%7}, {%8,%9}, {%0,%1,%2,%3};"
                 : "+f"(d[0]), "+f"(d[1]), "+f"(d[2]), "+f"(d[3])
                 : "r"(a[0]), "r"(a[1]), "r"(a[2]), "r"(a[3]), "r"(b[0]), "r"(b[1]));
}

// ---------------- pool (stage-1 routing input only) ------------------------------
__global__ void pool_kernel(const float* __restrict__ X, float* __restrict__ P, int total_rows)
{
    int warp = (blockIdx.x * blockDim.x + threadIdx.x) >> 5;
    int lane = threadIdx.x & 31;
    if (warp >= total_rows) return;
    const float* row = X + (size_t)warp * HW;
    float s = 0.f;
    for (int i = lane; i < HW; i += 32) s += row[i];
    #pragma unroll
    for (int o = 16; o; o >>= 1) s += __shfl_down_sync(0xffffffffu, s, o);
    if (lane == 0) P[warp] = s * (1.0f / HW);
}

__global__ void route_kernel(const float* __restrict__ P, const float* __restrict__ Wr,
                             const float* __restrict__ br, float* __restrict__ RW, int C)
{
    int b = blockIdx.x, e = threadIdx.x >> 5, lane = threadIdx.x & 31;
    float s = 0.f;
    for (int c = lane; c < C; c += 32) s += P[b * C + c] * Wr[c * EE + e];
    #pragma unroll
    for (int o = 16; o; o >>= 1) s += __shfl_down_sync(0xffffffffu, s, o);
    if (lane == 0) RW[b * EE + e] = 1.0f / (1.0f + expf(-(s + br[e])));
}

// routing from pooling partials (4 n-blocks per row), C = 256
__global__ void route_pp_kernel(const float* __restrict__ PP, const float* __restrict__ Wr,
                                const float* __restrict__ br, float* __restrict__ RW)
{
    int b = blockIdx.x, e = threadIdx.x >> 5, lane = threadIdx.x & 31;
    float s = 0.f;
    for (int c = lane; c < 256; c += 32) {
        const float* p = PP + ((size_t)b * 256 + c) * 4;
        float pv = (p[0] + p[1] + p[2] + p[3]) * (1.0f / HW);
        s += pv * Wr[c * EE + e];
    }
    #pragma unroll
    for (int o = 16; o; o >>= 1) s += __shfl_down_sync(0xffffffffu, s, o);
    if (lane == 0) RW[b * EE + e] = 1.0f / (1.0f + expf(-(s + br[e])));
}

// ---------------- combine (K-major) -> bf16 hi/lo -------------------------------
__global__ void combine_bf16_kernel(const float* __restrict__ Wexp, const float* __restrict__ RW,
                                    bf16* __restrict__ CWh, bf16* __restrict__ CWl, int Wsz)
{
    __shared__ float rws[BB * EE];
    if (threadIdx.x < BB * EE) rws[threadIdx.x] = RW[threadIdx.x];
    __syncthreads();
    int idx = blockIdx.x * blockDim.x + threadIdx.x;
    if (idx >= Wsz / 4) return;
    float4 we[EE];
    #pragma unroll
    for (int e = 0; e < EE; e++) we[e] = ((const float4*)Wexp)[(size_t)e * (Wsz / 4) + idx];
    #pragma unroll 4
    for (int b = 0; b < BB; b++) {
        float4 a = make_float4(0.f, 0.f, 0.f, 0.f);
        #pragma unroll
        for (int e = 0; e < EE; e++) {
            float r = rws[b * EE + e];
            a.x = fmaf(r, we[e].x, a.x); a.y = fmaf(r, we[e].y, a.y);
            a.z = fmaf(r, we[e].z, a.z); a.w = fmaf(r, we[e].w, a.w);
        }
        bf16 h0 = __float2bfloat16(a.x), h1 = __float2bfloat16(a.y);
        bf16 h2 = __float2bfloat16(a.z), h3 = __float2bfloat16(a.w);
        float l0 = a.x - __bfloat162float(h0), l1 = a.y - __bfloat162float(h1);
        float l2 = a.z - __bfloat162float(h2), l3 = a.w - __bfloat162float(h3);
        size_t o = (size_t)b * Wsz + (size_t)idx * 4;
        CWh[o] = h0; CWh[o + 1] = h1; CWh[o + 2] = h2; CWh[o + 3] = h3;
        CWl[o] = __float2bfloat16(l0); CWl[o + 1] = __float2bfloat16(l1);
        CWl[o + 2] = __float2bfloat16(l2); CWl[o + 3] = __float2bfloat16(l3);
    }
}

// ---------------- combine for stage 2: k = r*256 + c ----------------------------
__global__ void combine2_kernel(const float* __restrict__ W2, const float* __restrict__ RW,
                                bf16* __restrict__ CWh, bf16* __restrict__ CWl)
{
    __shared__ float rws[BB * EE];
    if (threadIdx.x < BB * EE) rws[threadIdx.x] = RW[threadIdx.x];
    __syncthreads();
    int m = blockIdx.x, c = threadIdx.x;
    float w[EE][9];
    #pragma unroll
    for (int e = 0; e < EE; e++)
        #pragma unroll
        for (int r = 0; r < 9; r++)
            w[e][r] = W2[((size_t)e * 256 * 256 + m * 256 + c) * 9 + r];
    for (int b = 0; b < BB; b++) {
        float acc[9];
        #pragma unroll
        for (int r = 0; r < 9; r++) acc[r] = 0.f;
        #pragma unroll
        for (int e = 0; e < EE; e++) {
            float rv = rws[b * EE + e];
            #pragma unroll
            for (int r = 0; r < 9; r++) acc[r] = fmaf(rv, w[e][r], acc[r]);
        }
        size_t base = ((size_t)b * 256 + m) * 2304 + c;
        #pragma unroll
        for (int r = 0; r < 9; r++) {
            bf16 h = __float2bfloat16(acc[r]);
            float l = acc[r] - __bfloat162float(h);
            CWh[base + r * 256] = h;
            CWl[base + r * 256] = __float2bfloat16(l);
        }
    }
}

// ---------------- transpose-convert: src[b][K][196] f32 -> dst[b][224][K] bf16 --
__global__ void transpose_kernel(const float* __restrict__ src,
                                 bf16* __restrict__ dhi, bf16* __restrict__ dlo, int K)
{
    __shared__ float t[32][33];
    int b = blockIdx.z, k0 = blockIdx.x * 32, n0 = blockIdx.y * 32;
    int tx = threadIdx.x, ty = threadIdx.y;
    const float* s = src + (size_t)b * K * HW;
    #pragma unroll
    for (int i = 0; i < 4; i++) {
        int kl = ty + 8 * i, n = n0 + tx;
        t[kl][tx] = (n < HW) ? s[(size_t)(k0 + kl) * HW + n] : 0.f;
    }
    __syncthreads();
    #pragma unroll
    for (int i = 0; i < 4; i++) {
        int nl = ty + 8 * i;
        float v = t[tx][nl];
        bf16 h = __float2bfloat16(v);
        float l = v - __bfloat162float(h);
        size_t o = ((size_t)b * NP + (n0 + nl)) * K + k0 + tx;
        dhi[o] = h;
        dlo[o] = __float2bfloat16(l);
    }
}

// ---------------- stage-2 im2col-transpose: o1[b][256][196] -> xt[b][224][2304] -
__global__ void __launch_bounds__(256)
xt2_kernel(const float* __restrict__ o1, bf16* __restrict__ dhi, bf16* __restrict__ dlo)
{
    __shared__ float sm[128][57];
    const int ng = blockIdx.x, c0 = blockIdx.y * 128, b = blockIdx.z;
    const int tid = threadIdx.x, lane = tid & 31, wrp = tid >> 5;
    const int n0 = ng * 16;
    const int wy0 = n0 / 14 - 1;

    const float* src = o1 + ((size_t)b * 256 + c0) * HW;
    for (int i = tid; i < 128 * 56; i += 256) {
        int cl = i / 56, s = i - 56 * cl;
        int y = wy0 + s / 14, x = s - 14 * (s / 14);
        sm[cl][s] = (y >= 0 && y < 14) ? src[(size_t)cl * HW + y * 14 + x] : 0.f;
    }
    __syncthreads();

    for (int t = wrp; t < 576; t += 8) {
        int nl = t & 15, seg = t >> 4;
        int r = seg / 4, cg = seg & 3;
        int cl = cg * 32 + lane;
        int n = n0 + nl;
        int dy = r / 3 - 1, dx = r - (r / 3) * 3 - 1;
        int y = n / 14 + dy, x = n - 14 * (n / 14) + dx;
        float v = 0.f;
        if (n < HW && y >= 0 && y < 14 && x >= 0 && x < 14)
            v = sm[cl][(y - wy0) * 14 + x];
        bf16 h = __float2bfloat16(v);
        float l = v - __bfloat162float(h);
        size_t o = ((size_t)b * NP + n) * 2304 + r * 256 + c0 + cl;
        dhi[o] = h;
        dlo[o] = __float2bfloat16(l);
    }
}

// ---------------- warp-MMA GEMM, bf16 3-term, fused BN(+resid)+ReLU(+pool) ------
// WIDE: 128m x 112n tile, 8 warps 4m x 2n (warp 32m x 56n)  [stage 3]
// !WIDE: 128m x 56n tile, 8 warps 8m x 1n (warp 16m x 56n), B shared by all warps
template<bool WIDE, bool RESID, bool POOL>
__global__ void __launch_bounds__(256)
mma_kernel(const bf16* __restrict__ Ahg, const bf16* __restrict__ Alg,
           const bf16* __restrict__ Bhg, const bf16* __restrict__ Blg,
           float* __restrict__ dst, float* __restrict__ pp,
           const float* __restrict__ gam, const float* __restrict__ bet,
           const float* __restrict__ mu,  const float* __restrict__ var,
           const float* __restrict__ resid,
           int M_total, int K)
{
    constexpr int NT = WIDE ? 112 : 56;
    constexpr int S  = WIDE ? 2 : 1;

    __shared__ __align__(16) bf16 Ah[2][128][24];
    __shared__ __align__(16) bf16 Al[2][128][24];
    __shared__ __align__(16) bf16 Bh[2][NT][24];
    __shared__ __align__(16) bf16 Bl[2][NT][24];

    const int b     = blockIdx.z;
    const int nbase = blockIdx.y * NT;
    const int mbase = blockIdx.x * 128;
    const int tid   = threadIdx.x;
    const int wid   = tid >> 5, lane = tid & 31;
    const int wm    = WIDE ? (wid & 3) * 32 : wid * 16;
    const int wn    = WIDE ? (wid >> 2) * 56 : 0;
    const int nk    = K / 16;

    const bf16* gAh = Ahg + ((size_t)b * M_total + mbase) * K;
    const bf16* gAl = Alg + ((size_t)b * M_total + mbase) * K;
    const bf16* gBh = Bhg + ((size_t)b * NP + nbase) * K;
    const bf16* gBl = Blg + ((size_t)b * NP + nbase) * K;

    float acc[S][7][4];
    #pragma unroll
    for (int s = 0; s < S; s++)
        #pragma unroll
        for (int t = 0; t < 7; t++)
            #pragma unroll
            for (int i = 0; i < 4; i++) acc[s][t][i] = 0.f;

    auto fill = [&](int kt, int buf) {
        const int k0 = kt * 16;
        {
            int row = tid >> 1, ch = tid & 1;
            const size_t go = (size_t)row * K + k0 + ch * 8;
            cp16(&Ah[buf][row][ch * 8], gAh + go);
            cp16(&Al[buf][row][ch * 8], gAl + go);
        }
        if (tid < NT * 2) {
            int row = tid >> 1, ch = tid & 1;
            const size_t go = (size_t)row * K + k0 + ch * 8;
            cp16(&Bh[buf][row][ch * 8], gBh + go);
            cp16(&Bl[buf][row][ch * 8], gBl + go);
        }
    };

    fill(0, 0); CP_COMMIT();

    const int lm = lane & 15, lk = lane >> 4;
    const int ln = lane & 7,  lk2 = (lane >> 3) & 1;

    for (int kt = 0; kt < nk; kt++) {
        const int cur = kt & 1, nxt = cur ^ 1;
        const bool has = (kt + 1 < nk);
        if (has) { fill(kt + 1, nxt); CP_COMMIT(); }
        if (has) asm volatile("cp.async.wait_group 1;" ::: "memory");
        else     asm volatile("cp.async.wait_group 0;" ::: "memory");
        __syncthreads();

        uint32_t ah[S][4], al[S][4];
        #pragma unroll
        for (int s = 0; s < S; s++) {
            ldsm_x4(ah[s], smem_u32(&Ah[cur][wm + s * 16 + lm][lk * 8]));
            ldsm_x4(al[s], smem_u32(&Al[cur][wm + s * 16 + lm][lk * 8]));
        }
        uint32_t bh[7][2], bl[7][2];
        #pragma unroll
        for (int t = 0; t < 7; t++) {
            ldsm_x2(bh[t], smem_u32(&Bh[cur][wn + t * 8 + ln][lk2 * 8]));
            ldsm_x2(bl[t], smem_u32(&Bl[cur][wn + t * 8 + ln][lk2 * 8]));
        }
        #pragma unroll
        for (int s = 0; s < S; s++)
            #pragma unroll
            for (int t = 0; t < 7; t++) {
                mma_bf16(acc[s][t], ah[s], bh[t]);
                mma_bf16(acc[s][t], ah[s], bl[t]);
                mma_bf16(acc[s][t], al[s], bh[t]);
            }
        __syncthreads();
    }

    // ---- fused epilogue: BN (+resid) + ReLU (+pool partials), direct store ----
    const int tm = lane >> 2, tn2 = (lane & 3) * 2;
    #pragma unroll
    for (int s = 0; s < S; s++) {
        int r0 = mbase + wm + s * 16 + tm;
        int r1 = r0 + 8;
        float i0 = rsqrtf(var[r0] + EPS) * gam[r0];
        float b0 = bet[r0] - mu[r0] * i0;
        float i1 = rsqrtf(var[r1] + EPS) * gam[r1];
        float b1 = bet[r1] - mu[r1] * i1;
        size_t o0 = ((size_t)b * M_total + r0) * HW;
        size_t o1 = ((size_t)b * M_total + r1) * HW;
        float psum0 = 0.f, psum1 = 0.f;
        #pragma unroll
        for (int t = 0; t < 7; t++) {
            int n = nbase + wn + t * 8 + tn2;
            if (n < HW) {
                float2 v0, v1;
                v0.x = fmaf(acc[s][t][0], i0, b0);
                v0.y = fmaf(acc[s][t][1], i0, b0);
                v1.x = fmaf(acc[s][t][2], i1, b1);
                v1.y = fmaf(acc[s][t][3], i1, b1);
                if (RESID) {
                    v0.x += resid[o0 + n]; v0.y += resid[o0 + n + 1];
                    v1.x += resid[o1 + n]; v1.y += resid[o1 + n + 1];
                }
                v0.x = fmaxf(v0.x, 0.f); v0.y = fmaxf(v0.y, 0.f);
                v1.x = fmaxf(v1.x, 0.f); v1.y = fmaxf(v1.y, 0.f);
                *(float2*)(dst + o0 + n) = v0;
                *(float2*)(dst + o1 + n) = v1;
                if (POOL) { psum0 += v0.x + v0.y; psum1 += v1.x + v1.y; }
            }
        }
        if (POOL) {
            psum0 += __shfl_xor_sync(0xffffffffu, psum0, 1);
            psum0 += __shfl_xor_sync(0xffffffffu, psum0, 2);
            psum1 += __shfl_xor_sync(0xffffffffu, psum1, 1);
            psum1 += __shfl_xor_sync(0xffffffffu, psum1, 2);
            if ((lane & 3) == 0) {
                pp[((size_t)b * 256 + r0) * 4 + blockIdx.y] = psum0;
                pp[((size_t)b * 256 + r1) * 4 + blockIdx.y] = psum1;
            }
        }
    }
}

// ------------------------------------------------------------------------------
extern "C" void kernel_launch(void* const* d_in, const int* in_sizes, int n_in,
                              void* d_out, int out_size)
{
    const float* x    = (const float*)d_in[0];
    const float* w1   = (const float*)d_in[1];
    const float* w2   = (const float*)d_in[2];
    const float* w3   = (const float*)d_in[3];
    const float* r1w  = (const float*)d_in[4];
    const float* r1b  = (const float*)d_in[5];
    const float* r2w  = (const float*)d_in[6];
    const float* r2b  = (const float*)d_in[7];
    const float* r3w  = (const float*)d_in[8];
    const float* r3b  = (const float*)d_in[9];
    const float* bn1g = (const float*)d_in[10];
    const float* bn1b = (const float*)d_in[11];
    const float* bn1m = (const float*)d_in[12];
    const float* bn1v = (const float*)d_in[13];
    const float* bn2g = (const float*)d_in[14];
    const float* bn2b = (const float*)d_in[15];
    const float* bn2m = (const float*)d_in[16];
    const float* bn2v = (const float*)d_in[17];
    const float* bn3g = (const float*)d_in[18];
    const float* bn3b = (const float*)d_in[19];
    const float* bn3m = (const float*)d_in[20];
    const float* bn3v = (const float*)d_in[21];
    float* out = (float*)d_out;

    float *pooled, *rw, *o1, *o2, *pp;
    bf16 *cwh, *cwl, *xth, *xtl;
    cudaGetSymbolAddress((void**)&pooled, g_pooled);
    cudaGetSymbolAddress((void**)&rw,     g_rw);
    cudaGetSymbolAddress((void**)&o1,     g_o1);
    cudaGetSymbolAddress((void**)&o2,     g_o2);
    cudaGetSymbolAddress((void**)&pp,     g_pp);
    cudaGetSymbolAddress((void**)&cwh,    g_cwh);
    cudaGetSymbolAddress((void**)&cwl,    g_cwl);
    cudaGetSymbolAddress((void**)&xth,    g_xth);
    cudaGetSymbolAddress((void**)&xtl,    g_xtl);

    // ---- stage 1: 1x1, K=1024 -> M=256, fused BN+ReLU+pool ----
    pool_kernel<<<(BB * 1024 * 32 + 255) / 256, 256>>>(x, pooled, BB * 1024);
    route_kernel<<<BB, 256>>>(pooled, r1w, r1b, rw, 1024);
    combine_bf16_kernel<<<256, 256>>>(w1, rw, cwh, cwl, 256 * 1024);
    transpose_kernel<<<dim3(1024 / 32, 7, BB), dim3(32, 8)>>>(x, xth, xtl, 1024);
    mma_kernel<false, false, true><<<dim3(2, 4, BB), 256>>>(
        cwh, cwl, xth, xtl, o1, pp, bn1g, bn1b, bn1m, bn1v, nullptr, 256, 1024);

    // ---- stage 2: 3x3 (k = r*256+c), K=2304 -> M=256, fused BN+ReLU+pool ----
    route_pp_kernel<<<BB, 256>>>(pp, r2w, r2b, rw);
    combine2_kernel<<<256, 256>>>(w2, rw, cwh, cwl);
    xt2_kernel<<<dim3(14, 2, BB), 256>>>(o1, xth, xtl);
    mma_kernel<false, false, true><<<dim3(2, 4, BB), 256>>>(
        cwh, cwl, xth, xtl, o2, pp, bn2g, bn2b, bn2m, bn2v, nullptr, 256, 2304);

    // ---- stage 3: 1x1, K=256 -> M=1024, fused BN+resid+ReLU ----
    route_pp_kernel<<<BB, 256>>>(pp, r3w, r3b, rw);
    combine_bf16_kernel<<<256, 256>>>(w3, rw, cwh, cwl, 1024 * 256);
    transpose_kernel<<<dim3(256 / 32, 7, BB), dim3(32, 8)>>>(o2, xth, xtl, 256);
    mma_kernel<true, true, false><<<dim3(8, 2, BB), 256>>>(
        cwh, cwl, xth, xtl, out, nullptr, bn3g, bn3b, bn3m, bn3v, x, 1024, 256);
}

// round 10
// speedup vs baseline: 1.2730x; 1.2730x over previous
#include <cuda_runtime.h>
#include <cuda_bf16.h>
#include <math.h>
#include <stdint.h>

#define BB   32
#define EE   8
#define HW   196
#define NP   224          // padded N (196 -> 224)
#define EPS  1e-5f

typedef unsigned long long ull;
typedef __nv_bfloat16 bf16;

// ---------------- scratch (device globals; no runtime allocation) -------------
__device__ float g_pooled[BB * 1024];
__device__ float g_rw[BB * EE];
__device__ float g_o1[BB * 256 * HW];
__device__ float g_o2[BB * 256 * HW];
__device__ float g_part[2 * BB * 256 * HW];
__device__ bf16  g_cwh[BB * 256 * 2304];
__device__ bf16  g_cwl[BB * 256 * 2304];
__device__ bf16  g_xth[BB * NP * 1024];
__device__ bf16  g_xtl[BB * NP * 1024];

// ---------------- helpers -------------------------------------------------------
__device__ __forceinline__ void cp16(void* s, const void* g) {
    unsigned a = (unsigned)__cvta_generic_to_shared(s);
    asm volatile("cp.async.cg.shared.global [%0], [%1], 16;" :: "r"(a), "l"(g));
}
#define CP_COMMIT() asm volatile("cp.async.commit_group;" ::: "memory")

__device__ __forceinline__ uint32_t smem_u32(const void* p) {
    return (uint32_t)__cvta_generic_to_shared(p);
}
__device__ __forceinline__ void ldsm_x4(uint32_t* r, uint32_t a) {
    asm volatile("ldmatrix.sync.aligned.m8n8.x4.shared.b16 {%0,%1,%2,%3}, [%4];"
                 : "=r"(r[0]), "=r"(r[1]), "=r"(r[2]), "=r"(r[3]) : "r"(a));
}
__device__ __forceinline__ void ldsm_x2(uint32_t* r, uint32_t a) {
    asm volatile("ldmatrix.sync.aligned.m8n8.x2.shared.b16 {%0,%1}, [%2];"
                 : "=r"(r[0]), "=r"(r[1]) : "r"(a));
}
__device__ __forceinline__ void mma_bf16(float* d, const uint32_t* a, const uint32_t* b) {
    asm volatile("mma.sync.aligned.m16n8k16.row.col.f32.bf16.bf16.f32 "
                 "{%0,%1,%2,%3}, {%4,%5,%6,%7}, {%8,%9}, {%0,%1,%2,%3};"
                 : "+f"(d[0]), "+f"(d[1]), "+f"(d[2]), "+f"(d[3])
                 : "r"(a[0]), "r"(a[1]), "r"(a[2]), "r"(a[3]), "r"(b[0]), "r"(b[1]));
}

// ---------------- pool / route --------------------------------------------------
__global__ void pool_kernel(const float* __restrict__ X, float* __restrict__ P, int total_rows)
{
    int warp = (blockIdx.x * blockDim.x + threadIdx.x) >> 5;
    int lane = threadIdx.x & 31;
    if (warp >= total_rows) return;
    const float* row = X + (size_t)warp * HW;
    float s = 0.f;
    for (int i = lane; i < HW; i += 32) s += row[i];
    #pragma unroll
    for (int o = 16; o; o >>= 1) s += __shfl_down_sync(0xffffffffu, s, o);
    if (lane == 0) P[warp] = s * (1.0f / HW);
}

__global__ void route_kernel(const float* __restrict__ P, const float* __restrict__ Wr,
                             const float* __restrict__ br, float* __restrict__ RW, int C)
{
    int b = blockIdx.x, e = threadIdx.x >> 5, lane = threadIdx.x & 31;
    float s = 0.f;
    for (int c = lane; c < C; c += 32) s += P[b * C + c] * Wr[c * EE + e];
    #pragma unroll
    for (int o = 16; o; o >>= 1) s += __shfl_down_sync(0xffffffffu, s, o);
    if (lane == 0) RW[b * EE + e] = 1.0f / (1.0f + expf(-(s + br[e])));
}

// ---------------- combine (K-major) -> bf16 hi/lo -------------------------------
__global__ void combine_bf16_kernel(const float* __restrict__ Wexp, const float* __restrict__ RW,
                                    bf16* __restrict__ CWh, bf16* __restrict__ CWl, int Wsz)
{
    __shared__ float rws[BB * EE];
    if (threadIdx.x < BB * EE) rws[threadIdx.x] = RW[threadIdx.x];
    __syncthreads();
    int idx = blockIdx.x * blockDim.x + threadIdx.x;
    if (idx >= Wsz / 4) return;
    float4 we[EE];
    #pragma unroll
    for (int e = 0; e < EE; e++) we[e] = ((const float4*)Wexp)[(size_t)e * (Wsz / 4) + idx];
    #pragma unroll 4
    for (int b = 0; b < BB; b++) {
        float4 a = make_float4(0.f, 0.f, 0.f, 0.f);
        #pragma unroll
        for (int e = 0; e < EE; e++) {
            float r = rws[b * EE + e];
            a.x = fmaf(r, we[e].x, a.x); a.y = fmaf(r, we[e].y, a.y);
            a.z = fmaf(r, we[e].z, a.z); a.w = fmaf(r, we[e].w, a.w);
        }
        bf16 h0 = __float2bfloat16(a.x), h1 = __float2bfloat16(a.y);
        bf16 h2 = __float2bfloat16(a.z), h3 = __float2bfloat16(a.w);
        float l0 = a.x - __bfloat162float(h0), l1 = a.y - __bfloat162float(h1);
        float l2 = a.z - __bfloat162float(h2), l3 = a.w - __bfloat162float(h3);
        size_t o = (size_t)b * Wsz + (size_t)idx * 4;
        CWh[o] = h0; CWh[o + 1] = h1; CWh[o + 2] = h2; CWh[o + 3] = h3;
        CWl[o] = __float2bfloat16(l0); CWl[o + 1] = __float2bfloat16(l1);
        CWl[o + 2] = __float2bfloat16(l2); CWl[o + 3] = __float2bfloat16(l3);
    }
}

// ---------------- combine for stage 2: k = r*256 + c ----------------------------
__global__ void combine2_kernel(const float* __restrict__ W2, const float* __restrict__ RW,
                                bf16* __restrict__ CWh, bf16* __restrict__ CWl)
{
    __shared__ float rws[BB * EE];
    if (threadIdx.x < BB * EE) rws[threadIdx.x] = RW[threadIdx.x];
    __syncthreads();
    int m = blockIdx.x, c = threadIdx.x;
    float w[EE][9];
    #pragma unroll
    for (int e = 0; e < EE; e++)
        #pragma unroll
        for (int r = 0; r < 9; r++)
            w[e][r] = W2[((size_t)e * 256 * 256 + m * 256 + c) * 9 + r];
    for (int b = 0; b < BB; b++) {
        float acc[9];
        #pragma unroll
        for (int r = 0; r < 9; r++) acc[r] = 0.f;
        #pragma unroll
        for (int e = 0; e < EE; e++) {
            float rv = rws[b * EE + e];
            #pragma unroll
            for (int r = 0; r < 9; r++) acc[r] = fmaf(rv, w[e][r], acc[r]);
        }
        size_t base = ((size_t)b * 256 + m) * 2304 + c;
        #pragma unroll
        for (int r = 0; r < 9; r++) {
            bf16 h = __float2bfloat16(acc[r]);
            float l = acc[r] - __bfloat162float(h);
            CWh[base + r * 256] = h;
            CWl[base + r * 256] = __float2bfloat16(l);
        }
    }
}

// ---------------- transpose-convert: src[b][K][196] f32 -> dst[b][224][K] bf16 --
__global__ void transpose_kernel(const float* __restrict__ src,
                                 bf16* __restrict__ dhi, bf16* __restrict__ dlo, int K)
{
    __shared__ float t[32][33];
    int b = blockIdx.z, k0 = blockIdx.x * 32, n0 = blockIdx.y * 32;
    int tx = threadIdx.x, ty = threadIdx.y;
    const float* s = src + (size_t)b * K * HW;
    #pragma unroll
    for (int i = 0; i < 4; i++) {
        int kl = ty + 8 * i, n = n0 + tx;
        t[kl][tx] = (n < HW) ? s[(size_t)(k0 + kl) * HW + n] : 0.f;
    }
    __syncthreads();
    #pragma unroll
    for (int i = 0; i < 4; i++) {
        int nl = ty + 8 * i;
        float v = t[tx][nl];
        bf16 h = __float2bfloat16(v);
        float l = v - __bfloat162float(h);
        size_t o = ((size_t)b * NP + (n0 + nl)) * K + k0 + tx;
        dhi[o] = h;
        dlo[o] = __float2bfloat16(l);
    }
}

// ---------------- warp-MMA GEMM: 128m x 112n block tile, bf16 3-term ------------
// (R7-proven configuration) 8 warps (4m x 2n); warp tile 32m x 56n.
// CONV3: B synthesized on the fly from transposed o1 [b][224][256] with
//        k = r*256 + c; each 16-k tile lies within one tap r.
template<bool CONV3, bool FUSE>
__global__ void __launch_bounds__(256)
mma_kernel(const bf16* __restrict__ Ahg, const bf16* __restrict__ Alg,
           const bf16* __restrict__ Bhg, const bf16* __restrict__ Blg,
           float* __restrict__ dst,
           const float* __restrict__ gam, const float* __restrict__ bet,
           const float* __restrict__ mu,  const float* __restrict__ var,
           const float* __restrict__ resid,
           int M_total, int K, int Kc)
{
    __shared__ __align__(16) bf16 Ah[2][128][24];
    __shared__ __align__(16) bf16 Al[2][128][24];
    __shared__ __align__(16) bf16 Bh[2][112][24];
    __shared__ __align__(16) bf16 Bl[2][112][24];

    const int b     = blockIdx.z;
    const int split = blockIdx.y >> 1;
    const int nbase = (blockIdx.y & 1) * 112;
    const int mbase = blockIdx.x * 128;
    const int tid   = threadIdx.x;
    const int wid   = tid >> 5, lane = tid & 31;
    const int wm    = (wid & 3) * 32;
    const int wn    = (wid >> 2) * 56;
    const int kbeg  = split * Kc;
    const int nk    = Kc / 16;

    const bf16* gAh = Ahg + ((size_t)b * M_total + mbase) * K + kbeg;
    const bf16* gAl = Alg + ((size_t)b * M_total + mbase) * K + kbeg;
    // CONV3: base of transposed o1 (row stride 256); else: B slab at nbase/kbeg
    const bf16* gBh = CONV3 ? (Bhg + (size_t)b * NP * 256)
                            : (Bhg + ((size_t)b * NP + nbase) * K + kbeg);
    const bf16* gBl = CONV3 ? (Blg + (size_t)b * NP * 256)
                            : (Blg + ((size_t)b * NP + nbase) * K + kbeg);

    float acc[2][7][4];
    #pragma unroll
    for (int s = 0; s < 2; s++)
        #pragma unroll
        for (int t = 0; t < 7; t++)
            #pragma unroll
            for (int i = 0; i < 4; i++) acc[s][t][i] = 0.f;

    auto fill = [&](int kt, int buf) {
        const int k0 = kt * 16;
        {
            int row = tid >> 1, ch = tid & 1;
            const size_t go = (size_t)row * K + k0 + ch * 8;
            cp16(&Ah[buf][row][ch * 8], gAh + go);
            cp16(&Al[buf][row][ch * 8], gAl + go);
        }
        if (tid < 224) {
            int row = tid >> 1, ch = tid & 1;
            if (!CONV3) {
                const size_t go = (size_t)row * K + k0 + ch * 8;
                cp16(&Bh[buf][row][ch * 8], gBh + go);
                cp16(&Bl[buf][row][ch * 8], gBl + go);
            } else {
                const int ktg = (kbeg >> 4) + kt;     // global 16-k tile
                const int r  = ktg >> 4;              // tap index 0..8
                const int c0 = (ktg & 15) << 4;       // channel base
                const int n  = nbase + row;
                const int oy = n / 14, ox = n - 14 * oy;
                const int iy = oy + r / 3 - 1;
                const int ix = ox + (r - 3 * (r / 3)) - 1;
                if (n < HW && (unsigned)iy < 14u && (unsigned)ix < 14u) {
                    const size_t go = (size_t)(iy * 14 + ix) * 256 + c0 + ch * 8;
                    cp16(&Bh[buf][row][ch * 8], gBh + go);
                    cp16(&Bl[buf][row][ch * 8], gBl + go);
                } else {
                    const uint4 z = make_uint4(0, 0, 0, 0);
                    *(uint4*)&Bh[buf][row][ch * 8] = z;
                    *(uint4*)&Bl[buf][row][ch * 8] = z;
                }
            }
        }
    };

    fill(0, 0); CP_COMMIT();

    const int lm = lane & 15, lk = lane >> 4;
    const int ln = lane & 7,  lk2 = (lane >> 3) & 1;

    for (int kt = 0; kt < nk; kt++) {
        const int cur = kt & 1, nxt = cur ^ 1;
        const bool has = (kt + 1 < nk);
        if (has) { fill(kt + 1, nxt); CP_COMMIT(); }
        if (has) asm volatile("cp.async.wait_group 1;" ::: "memory");
        else     asm volatile("cp.async.wait_group 0;" ::: "memory");
        __syncthreads();

        uint32_t ah[2][4], al[2][4];
        #pragma unroll
        for (int s = 0; s < 2; s++) {
            ldsm_x4(ah[s], smem_u32(&Ah[cur][wm + s * 16 + lm][lk * 8]));
            ldsm_x4(al[s], smem_u32(&Al[cur][wm + s * 16 + lm][lk * 8]));
        }
        uint32_t bh[7][2], bl[7][2];
        #pragma unroll
        for (int t = 0; t < 7; t++) {
            ldsm_x2(bh[t], smem_u32(&Bh[cur][wn + t * 8 + ln][lk2 * 8]));
            ldsm_x2(bl[t], smem_u32(&Bl[cur][wn + t * 8 + ln][lk2 * 8]));
        }
        #pragma unroll
        for (int s = 0; s < 2; s++)
            #pragma unroll
            for (int t = 0; t < 7; t++) {
                mma_bf16(acc[s][t], ah[s], bh[t]);
                mma_bf16(acc[s][t], ah[s], bl[t]);
                mma_bf16(acc[s][t], al[s], bh[t]);
            }
        __syncthreads();
    }

    // ---- epilogue ----
    const int tm = lane >> 2, tn2 = (lane & 3) * 2;
    if (FUSE) {
        #pragma unroll
        for (int s = 0; s < 2; s++) {
            int r0 = mbase + wm + s * 16 + tm;
            int r1 = r0 + 8;
            float i0 = rsqrtf(var[r0] + EPS) * gam[r0];
            float b0 = bet[r0] - mu[r0] * i0;
            float i1 = rsqrtf(var[r1] + EPS) * gam[r1];
            float b1 = bet[r1] - mu[r1] * i1;
            size_t o0 = ((size_t)b * M_total + r0) * HW;
            size_t o1 = ((size_t)b * M_total + r1) * HW;
            #pragma unroll
            for (int t = 0; t < 7; t++) {
                int n = nbase + wn + t * 8 + tn2;
                if (n < HW) {
                    float2 v0, v1;
                    v0.x = fmaxf(fmaf(acc[s][t][0], i0, b0) + resid[o0 + n],     0.f);
                    v0.y = fmaxf(fmaf(acc[s][t][1], i0, b0) + resid[o0 + n + 1], 0.f);
                    v1.x = fmaxf(fmaf(acc[s][t][2], i1, b1) + resid[o1 + n],     0.f);
                    v1.y = fmaxf(fmaf(acc[s][t][3], i1, b1) + resid[o1 + n + 1], 0.f);
                    *(float2*)(dst + o0 + n) = v0;
                    *(float2*)(dst + o1 + n) = v1;
                }
            }
        }
    } else {
        #pragma unroll
        for (int s = 0; s < 2; s++) {
            int r0 = mbase + wm + s * 16 + tm;
            size_t o0 = (((size_t)split * BB + b) * M_total + r0) * HW;
            size_t o1 = o0 + 8 * HW;
            #pragma unroll
            for (int t = 0; t < 7; t++) {
                int n = nbase + wn + t * 8 + tn2;
                if (n < HW) {
                    *(float2*)(dst + o0 + n) = make_float2(acc[s][t][0], acc[s][t][1]);
                    *(float2*)(dst + o1 + n) = make_float2(acc[s][t][2], acc[s][t][3]);
                }
            }
        }
    }
}

// ---------------- split-K(2) reduce + BN + ReLU + next-stage pool ----------------
__global__ void reduce_bn_relu_pool(const float* __restrict__ Part, float* __restrict__ Out,
                                    float* __restrict__ Pooled,
                                    const float* __restrict__ gam, const float* __restrict__ bet,
                                    const float* __restrict__ mu,  const float* __restrict__ var,
                                    int rows)
{
    int gid  = blockIdx.x * 4 + (threadIdx.x >> 5);
    int lane = threadIdx.x & 31;
    if (gid >= rows) return;
    int m = gid & 255;
    const size_t stride = (size_t)rows * HW;
    float inv  = rsqrtf(var[m] + EPS) * gam[m];
    float beta = bet[m] - mu[m] * inv;
    size_t base = (size_t)gid * HW;
    float psum = 0.f;
    for (int n = lane; n < HW; n += 32) {
        float s = Part[base + n] + Part[stride + base + n];
        float v = fmaxf(fmaf(s, inv, beta), 0.f);
        Out[base + n] = v;
        psum += v;
    }
    #pragma unroll
    for (int o = 16; o; o >>= 1) psum += __shfl_down_sync(0xffffffffu, psum, o);
    if (lane == 0) Pooled[gid] = psum * (1.0f / HW);
}

// ------------------------------------------------------------------------------
extern "C" void kernel_launch(void* const* d_in, const int* in_sizes, int n_in,
                              void* d_out, int out_size)
{
    const float* x    = (const float*)d_in[0];
    const float* w1   = (const float*)d_in[1];
    const float* w2   = (const float*)d_in[2];
    const float* w3   = (const float*)d_in[3];
    const float* r1w  = (const float*)d_in[4];
    const float* r1b  = (const float*)d_in[5];
    const float* r2w  = (const float*)d_in[6];
    const float* r2b  = (const float*)d_in[7];
    const float* r3w  = (const float*)d_in[8];
    const float* r3b  = (const float*)d_in[9];
    const float* bn1g = (const float*)d_in[10];
    const float* bn1b = (const float*)d_in[11];
    const float* bn1m = (const float*)d_in[12];
    const float* bn1v = (const float*)d_in[13];
    const float* bn2g = (const float*)d_in[14];
    const float* bn2b = (const float*)d_in[15];
    const float* bn2m = (const float*)d_in[16];
    const float* bn2v = (const float*)d_in[17];
    const float* bn3g = (const float*)d_in[18];
    const float* bn3b = (const float*)d_in[19];
    const float* bn3m = (const float*)d_in[20];
    const float* bn3v = (const float*)d_in[21];
    float* out = (float*)d_out;

    float *pooled, *rw, *o1, *o2, *part;
    bf16 *cwh, *cwl, *xth, *xtl;
    cudaGetSymbolAddress((void**)&pooled, g_pooled);
    cudaGetSymbolAddress((void**)&rw,     g_rw);
    cudaGetSymbolAddress((void**)&o1,     g_o1);
    cudaGetSymbolAddress((void**)&o2,     g_o2);
    cudaGetSymbolAddress((void**)&part,   g_part);
    cudaGetSymbolAddress((void**)&cwh,    g_cwh);
    cudaGetSymbolAddress((void**)&cwl,    g_cwl);
    cudaGetSymbolAddress((void**)&xth,    g_xth);
    cudaGetSymbolAddress((void**)&xtl,    g_xtl);

    const int ROWS = BB * 256;

    // ---- stage 1: 1x1, K=1024 -> M=256, split-K=2 ----
    pool_kernel<<<(BB * 1024 * 32 + 255) / 256, 256>>>(x, pooled, BB * 1024);
    route_kernel<<<BB, 256>>>(pooled, r1w, r1b, rw, 1024);
    combine_bf16_kernel<<<256, 256>>>(w1, rw, cwh, cwl, 256 * 1024);
    transpose_kernel<<<dim3(1024 / 32, 7, BB), dim3(32, 8)>>>(x, xth, xtl, 1024);
    mma_kernel<false, false><<<dim3(2, 4, BB), 256>>>(
        cwh, cwl, xth, xtl, part, nullptr, nullptr, nullptr, nullptr, nullptr,
        256, 1024, 512);
    reduce_bn_relu_pool<<<ROWS / 4, 128>>>(part, o1, pooled, bn1g, bn1b, bn1m, bn1v, ROWS);

    // ---- stage 2: 3x3 (k = r*256+c), K=2304 -> M=256, split-K=2 ----
    // B synthesized inside the MMA from plain-transposed o1 (no im2col buffer)
    route_kernel<<<BB, 256>>>(pooled, r2w, r2b, rw, 256);
    combine2_kernel<<<256, 256>>>(w2, rw, cwh, cwl);
    transpose_kernel<<<dim3(256 / 32, 7, BB), dim3(32, 8)>>>(o1, xth, xtl, 256);
    mma_kernel<true, false><<<dim3(2, 4, BB), 256>>>(
        cwh, cwl, xth, xtl, part, nullptr, nullptr, nullptr, nullptr, nullptr,
        256, 2304, 1152);
    reduce_bn_relu_pool<<<ROWS / 4, 128>>>(part, o2, pooled, bn2g, bn2b, bn2m, bn2v, ROWS);

    // ---- stage 3: 1x1, K=256 -> M=1024, fused BN+resid+ReLU ----
    route_kernel<<<BB, 256>>>(pooled, r3w, r3b, rw, 256);
    combine_bf16_kernel<<<256, 256>>>(w3, rw, cwh, cwl, 1024 * 256);
    transpose_kernel<<<dim3(256 / 32, 7, BB), dim3(32, 8)>>>(o2, xth, xtl, 256);
    mma_kernel<false, true><<<dim3(8, 2, BB), 256>>>(
        cwh, cwl, xth, xtl, out, bn3g, bn3b, bn3m, bn3v, x, 1024, 256, 256);
}